// round 1
// baseline (speedup 1.0000x reference)
#include <cuda_runtime.h>
#include <cuda_bf16.h>
#include <math.h>

// ---------------- problem constants ----------------
#define NQ   300
#define BSZ  8
#define DIM  256
#define NH   8
#define DH   32
#define NLV  4
#define NPT  8
#define DFF  1024
#define STOT 13294
#define NTOK (NQ*BSZ)          // 2400
#define TOKF (NTOK*DIM)        // 614400

// ---------------- scratch (static device globals; no allocations) ----------------
__device__ float g_qbuf [TOKF];
__device__ float g_qh   [TOKF];
__device__ float g_kh   [TOKF];
__device__ float g_vh   [TOKF];
__device__ float g_sain [TOKF];
__device__ float g_saout[TOKF];
__device__ float g_tgt2 [TOKF];
__device__ float g_q2   [TOKF];
__device__ float g_off  [NTOK*512];
__device__ float g_awl  [TOKF];
__device__ float g_value[(long)BSZ*STOT*DIM];   // 27,226,112 floats
__device__ float g_cain [TOKF];
__device__ float g_caout[TOKF];
__device__ float g_tgt3 [TOKF];
__device__ float g_f1   [NTOK*DFF];
__device__ float g_f2   [TOKF];

// ---------------- generic fp32 GEMM: C = A(MxK) * W(NxK)^T + bias ----------------
// 128x64 tile, BK=16, 256 threads, 8x4 per thread.
// EPI: 0 = plain, 1 = relu, 2 = head-permute ([b][h][q][d]), 3 = pad-mask zero
template<int EPI>
__global__ void __launch_bounds__(256) gemm_k(
    const float* __restrict__ A, int lda, long aSz,
    const float* __restrict__ W, int ldw,
    const float* __restrict__ bias,
    float* __restrict__ C, int ldc, long cSz,
    int M, int N, int K,
    const unsigned char* __restrict__ mask, long mSz)
{
    __shared__ float As[16][132];
    __shared__ float Bs[16][68];
    const int bm = blockIdx.y * 128;
    const int bn = blockIdx.x * 64;
    A += (long)blockIdx.z * aSz;
    C += (long)blockIdx.z * cSz;

    const int tid = threadIdx.x;
    const int tx  = tid & 15;        // 16 -> 64 cols (4 each)
    const int ty  = tid >> 4;        // 16 -> 128 rows (8 each)
    const int ra  = tid >> 2;        // 0..63
    const int ca  = (tid & 3) << 2;  // 0,4,8,12

    float acc[8][4];
#pragma unroll
    for (int i = 0; i < 8; i++)
#pragma unroll
        for (int j = 0; j < 4; j++) acc[i][j] = 0.f;

    const bool ga0 = (bm + ra)      < M;
    const bool ga1 = (bm + ra + 64) < M;
    const bool gw  = (bn + ra)      < N;
    const float* a0p = A + (long)(bm + ra) * lda + ca;
    const float* a1p = a0p + (long)64 * lda;
    const float* wp  = W + (long)(bn + ra) * ldw + ca;

    for (int k0 = 0; k0 < K; k0 += 16) {
        float4 av0 = ga0 ? *(const float4*)(a0p + k0) : make_float4(0.f,0.f,0.f,0.f);
        float4 av1 = ga1 ? *(const float4*)(a1p + k0) : make_float4(0.f,0.f,0.f,0.f);
        float4 wv  = gw  ? *(const float4*)(wp  + k0) : make_float4(0.f,0.f,0.f,0.f);

        __syncthreads();   // previous compute done
        As[ca+0][ra]    = av0.x; As[ca+1][ra]    = av0.y; As[ca+2][ra]    = av0.z; As[ca+3][ra]    = av0.w;
        As[ca+0][ra+64] = av1.x; As[ca+1][ra+64] = av1.y; As[ca+2][ra+64] = av1.z; As[ca+3][ra+64] = av1.w;
        Bs[ca+0][ra]    = wv.x;  Bs[ca+1][ra]    = wv.y;  Bs[ca+2][ra]    = wv.z;  Bs[ca+3][ra]    = wv.w;
        __syncthreads();

#pragma unroll
        for (int kk = 0; kk < 16; kk++) {
            float4 b4 = *(const float4*)&Bs[kk][tx*4];
            float4 a0 = *(const float4*)&As[kk][ty*8];
            float4 a1 = *(const float4*)&As[kk][ty*8 + 4];
            float ar[8] = {a0.x,a0.y,a0.z,a0.w,a1.x,a1.y,a1.z,a1.w};
            float br[4] = {b4.x,b4.y,b4.z,b4.w};
#pragma unroll
            for (int i = 0; i < 8; i++)
#pragma unroll
                for (int j = 0; j < 4; j++)
                    acc[i][j] = fmaf(ar[i], br[j], acc[i][j]);
        }
    }

#pragma unroll
    for (int i = 0; i < 8; i++) {
        int r = bm + ty*8 + i;
        if (r < M) {
            bool mz = false;
            if (EPI == 3) mz = (mask[(long)blockIdx.z * mSz + r] != 0);
#pragma unroll
            for (int j = 0; j < 4; j++) {
                int n = bn + tx*4 + j;
                float v = acc[i][j] + bias[n];
                if (EPI == 1) v = fmaxf(v, 0.f);
                if (EPI == 3 && mz) v = 0.f;
                if (EPI == 2) {
                    int q = r >> 3, bb = r & 7, hh = n >> 5, d = n & 31;
                    C[(((long)(bb*NH + hh))*NQ + q)*DH + d] = v;
                } else {
                    C[(long)r * ldc + n] = v;
                }
            }
        }
    }
}

static inline void launch_gemm(int epi,
    const float* A, int lda, long aSz,
    const float* W, const float* bias,
    float* C, int ldc, long cSz,
    int M, int N, int K, int nz,
    const unsigned char* mask, long mSz)
{
    dim3 grid((N + 63) / 64, (M + 127) / 128, nz);
    switch (epi) {
        case 0: gemm_k<0><<<grid,256>>>(A,lda,aSz,W,K,bias,C,ldc,cSz,M,N,K,mask,mSz); break;
        case 1: gemm_k<1><<<grid,256>>>(A,lda,aSz,W,K,bias,C,ldc,cSz,M,N,K,mask,mSz); break;
        case 2: gemm_k<2><<<grid,256>>>(A,lda,aSz,W,K,bias,C,ldc,cSz,M,N,K,mask,mSz); break;
        case 3: gemm_k<3><<<grid,256>>>(A,lda,aSz,W,K,bias,C,ldc,cSz,M,N,K,mask,mSz); break;
    }
}

// ---------------- elementwise ----------------
__global__ void add_kernel(const float* __restrict__ a, const float* __restrict__ b,
                           float* __restrict__ o, int n)
{
    int i = blockIdx.x * blockDim.x + threadIdx.x;
    if (i < n) o[i] = a[i] + b[i];
}

// query2[(b*NQ+q)*D + d] = tgt2[(q*BS+b)*D + d] + mask[(q*BS+b)*D + d]
__global__ void permadd_kernel(const float* __restrict__ t2, const float* __restrict__ msk,
                               float* __restrict__ q2)
{
    int i = blockIdx.x * 256 + threadIdx.x;
    if (i >= TOKF) return;
    int d = i & 255;
    int t = i >> 8;
    int q = t >> 3, b = t & 7;
    q2[((long)(b*NQ + q) << 8) + d] = t2[i] + msk[i];
}

// ---------------- residual + layernorm: out[t] = LN(A[t] + B[..]) ----------------
__global__ void __launch_bounds__(256) ln_kernel(
    const float* __restrict__ A, const float* __restrict__ B, int bBQ,
    const float* __restrict__ g, const float* __restrict__ be,
    float* __restrict__ out)
{
    int t = blockIdx.x * 8 + (threadIdx.x >> 5);
    int lane = threadIdx.x & 31;
    if (t >= NTOK) return;
    const float* ap = A + (long)t * DIM + lane*8;
    long bo;
    if (bBQ) { int q = t >> 3, b = t & 7; bo = (long)(b*NQ + q) * DIM; }
    else     { bo = (long)t * DIM; }
    const float* bp = B + bo + lane*8;

    float4 x0 = *(const float4*)ap,      x1 = *(const float4*)(ap + 4);
    float4 y0 = *(const float4*)bp,      y1 = *(const float4*)(bp + 4);
    float v[8] = {x0.x+y0.x, x0.y+y0.y, x0.z+y0.z, x0.w+y0.w,
                  x1.x+y1.x, x1.y+y1.y, x1.z+y1.z, x1.w+y1.w};
    float s = 0.f;
#pragma unroll
    for (int i = 0; i < 8; i++) s += v[i];
#pragma unroll
    for (int o = 16; o; o >>= 1) s += __shfl_xor_sync(0xffffffffu, s, o);
    float mu = s * (1.f/256.f);
    float s2 = 0.f;
#pragma unroll
    for (int i = 0; i < 8; i++) { float d = v[i] - mu; s2 += d*d; }
#pragma unroll
    for (int o = 16; o; o >>= 1) s2 += __shfl_xor_sync(0xffffffffu, s2, o);
    float inv = rsqrtf(s2 * (1.f/256.f) + 1e-5f);
    int c0 = lane*8;
    float* op = out + (long)t * DIM + c0;
#pragma unroll
    for (int i = 0; i < 8; i++)
        op[i] = (v[i] - mu) * inv * g[c0+i] + be[c0+i];
}

// ---------------- fused self-attention ----------------
// grid = 64 (b,h) * 2 halves; block 256; K/V/Q resident in smem.
__global__ void __launch_bounds__(256) attn_kernel(
    const float* __restrict__ qh, const float* __restrict__ kh,
    const float* __restrict__ vh, float* __restrict__ sa_in)
{
    extern __shared__ float sm[];
    const int bh   = blockIdx.x >> 1;
    const int half = blockIdx.x & 1;
    const int b = bh >> 3, h = bh & 7;
    float* Ks = sm;                 // 300*36
    float* Vs = Ks + 300*36;        // 300*36
    float* Qs = Vs + 300*36;        // 150*32
    float* Ps = Qs + 150*32;        // 8*320

    const float scale = 0.17677669529663687f;  // 1/sqrt(32)
    const float* Kg = kh + (long)bh * NQ * DH;
    const float* Vg = vh + (long)bh * NQ * DH;
    const float* Qg = qh + (long)bh * NQ * DH + (long)half * 150 * DH;
    const int tid = threadIdx.x;

    for (int i = tid; i < 2400; i += 256) {           // 300*32/4 float4s
        int r = i >> 3, c4 = (i & 7) << 2;
        float4 kv = *(const float4*)(Kg + r*32 + c4);
        float4 vv = *(const float4*)(Vg + r*32 + c4);
        *(float4*)(Ks + r*36 + c4) = kv;
        *(float4*)(Vs + r*36 + c4) = vv;
    }
    for (int i = tid; i < 1200; i += 256) {           // 150*32/4
        int r = i >> 3, c4 = (i & 7) << 2;
        float4 qv = *(const float4*)(Qg + r*32 + c4);
        qv.x *= scale; qv.y *= scale; qv.z *= scale; qv.w *= scale;
        *(float4*)(Qs + r*32 + c4) = qv;
    }
    __syncthreads();

    const int warp = tid >> 5, lane = tid & 31;
    float* Pw = Ps + warp * 320;

    for (int q = warp; q < 150; q += 8) {
        float4 qr[8];
#pragma unroll
        for (int d4 = 0; d4 < 8; d4++) qr[d4] = *(const float4*)(Qs + q*32 + d4*4);

        float sc[10];
#pragma unroll
        for (int j = 0; j < 10; j++) {
            int k = j*32 + lane;
            float s = -1e30f;
            if (k < 300) {
                s = 0.f;
#pragma unroll
                for (int d4 = 0; d4 < 8; d4++) {
                    float4 kv = *(const float4*)(Ks + k*36 + d4*4);
                    s = fmaf(qr[d4].x, kv.x, s);
                    s = fmaf(qr[d4].y, kv.y, s);
                    s = fmaf(qr[d4].z, kv.z, s);
                    s = fmaf(qr[d4].w, kv.w, s);
                }
            }
            sc[j] = s;
        }
        float m = sc[0];
#pragma unroll
        for (int j = 1; j < 10; j++) m = fmaxf(m, sc[j]);
#pragma unroll
        for (int o = 16; o; o >>= 1) m = fmaxf(m, __shfl_xor_sync(0xffffffffu, m, o));
        float sum = 0.f;
#pragma unroll
        for (int j = 0; j < 10; j++) { sc[j] = expf(sc[j] - m); sum += sc[j]; }
#pragma unroll
        for (int o = 16; o; o >>= 1) sum += __shfl_xor_sync(0xffffffffu, sum, o);
        float inv = 1.f / sum;
#pragma unroll
        for (int j = 0; j < 10; j++) Pw[j*32 + lane] = sc[j] * inv;
        __syncwarp();

        float acc = 0.f;
#pragma unroll 4
        for (int k = 0; k < 300; k++)
            acc = fmaf(Pw[k], Vs[k*36 + lane], acc);

        int qg = half*150 + q;
        sa_in[((long)(qg*BSZ + b)) * DIM + h*DH + lane] = acc;
        __syncwarp();
    }
}

// ---------------- multi-scale deformable sampling ----------------
// block per (b,q), warp per head. lane = (l,p).
__global__ void __launch_bounds__(256) deform_kernel(
    const float* __restrict__ offp, const float* __restrict__ awl,
    const float* __restrict__ bbox, const float* __restrict__ value,
    const int* __restrict__ spatial, const int* __restrict__ lstart,
    float* __restrict__ ca_in)
{
    __shared__ float s_w[8][32][4];
    __shared__ int   s_i[8][32][4];
    int bq = blockIdx.x;
    int b = bq / NQ, q = bq - b*NQ;
    int warp = threadIdx.x >> 5, lane = threadIdx.x & 31;

    // softmax over 32 (l,p) per head
    float a = awl[(long)bq*256 + warp*32 + lane];
    float m = a;
#pragma unroll
    for (int o = 16; o; o >>= 1) m = fmaxf(m, __shfl_xor_sync(0xffffffffu, m, o));
    float e = expf(a - m);
    float s = e;
#pragma unroll
    for (int o = 16; o; o >>= 1) s += __shfl_xor_sync(0xffffffffu, s, o);
    float p = e / s;

    float ox = offp[(long)bq*512 + warp*64 + lane*2];
    float oy = offp[(long)bq*512 + warp*64 + lane*2 + 1];
    const float* rb = bbox + ((long)q*BSZ + b)*4;
    float r0 = rb[0], r1 = rb[1], r2 = rb[2], r3 = rb[3];

    int lvl = lane >> 3;
    int H = spatial[lvl*2], W = spatial[lvl*2 + 1], ls = lstart[lvl];
    float Wf = (float)W, Hf = (float)H;
    float x = (r0 + ox*0.0625f*r2) * Wf - 0.5f;   // off/NP * w * 0.5 = off*0.0625*w
    float y = (r1 + oy*0.0625f*r3) * Hf - 0.5f;
    float x0 = floorf(x), y0 = floorf(y);
    float fx = x - x0, fy = y - y0;

#pragma unroll
    for (int c = 0; c < 4; c++) {
        float xi = x0 + (float)(c & 1);
        float yi = y0 + (float)(c >> 1);
        float wgt = ((c & 1) ? fx : 1.f - fx) * ((c >> 1) ? fy : 1.f - fy);
        bool valid = (xi >= 0.f) && (xi < Wf) && (yi >= 0.f) && (yi < Hf);
        int xc = (int)fminf(fmaxf(xi, 0.f), Wf - 1.f);
        int yc = (int)fminf(fmaxf(yi, 0.f), Hf - 1.f);
        s_i[warp][lane][c] = ls + yc*W + xc;
        s_w[warp][lane][c] = valid ? wgt * p : 0.f;
    }
    __syncwarp();

    const float* vb = value + (long)b * STOT * DIM + warp*DH + lane;
    float acc = 0.f;
    for (int lp = 0; lp < 32; lp++) {
#pragma unroll
        for (int c = 0; c < 4; c++) {
            float wgt = s_w[warp][lp][c];          // warp-uniform broadcast
            if (wgt != 0.f)
                acc = fmaf(wgt, vb[(long)s_i[warp][lp][c] << 8], acc);
        }
    }
    ca_in[(long)bq*DIM + warp*DH + lane] = acc;
}

// ---------------- host orchestration ----------------
extern "C" void kernel_launch(void* const* d_in, const int* in_sizes, int n_in,
                              void* d_out, int out_size)
{
    const float* tgt        = (const float*)d_in[0];
    const float* qmask      = (const float*)d_in[1];
    const float* bbox       = (const float*)d_in[2];
    /* d_in[3] tgt_reference_masks: unused by reference */
    const float* memory     = (const float*)d_in[4];
    const float* in_proj_w  = (const float*)d_in[5];
    const float* in_proj_b  = (const float*)d_in[6];
    const float* out_sa_w   = (const float*)d_in[7];
    const float* out_sa_b   = (const float*)d_in[8];
    const float* norm2_g    = (const float*)d_in[9];
    const float* norm2_b    = (const float*)d_in[10];
    const float* value_w    = (const float*)d_in[11];
    const float* value_b    = (const float*)d_in[12];
    const float* off_w      = (const float*)d_in[13];
    const float* off_b      = (const float*)d_in[14];
    const float* aw_w       = (const float*)d_in[15];
    const float* aw_b       = (const float*)d_in[16];
    const float* out_ca_w   = (const float*)d_in[17];
    const float* out_ca_b   = (const float*)d_in[18];
    const float* norm1_g    = (const float*)d_in[19];
    const float* norm1_b    = (const float*)d_in[20];
    const float* lin1_w     = (const float*)d_in[21];
    const float* lin1_b     = (const float*)d_in[22];
    const float* lin2_w     = (const float*)d_in[23];
    const float* lin2_b     = (const float*)d_in[24];
    const float* norm3_g    = (const float*)d_in[25];
    const float* norm3_b    = (const float*)d_in[26];
    const unsigned char* pmask = (const unsigned char*)d_in[27];
    const int* spatial      = (const int*)d_in[28];
    const int* lstart       = (const int*)d_in[29];
    float* out = (float*)d_out;

    float *qbuf,*qh,*kh,*vh,*sain,*saout,*tgt2,*q2,*offb,*awl,*val,*cain,*caout,*tgt3,*f1,*f2;
    cudaGetSymbolAddress((void**)&qbuf,  g_qbuf);
    cudaGetSymbolAddress((void**)&qh,    g_qh);
    cudaGetSymbolAddress((void**)&kh,    g_kh);
    cudaGetSymbolAddress((void**)&vh,    g_vh);
    cudaGetSymbolAddress((void**)&sain,  g_sain);
    cudaGetSymbolAddress((void**)&saout, g_saout);
    cudaGetSymbolAddress((void**)&tgt2,  g_tgt2);
    cudaGetSymbolAddress((void**)&q2,    g_q2);
    cudaGetSymbolAddress((void**)&offb,  g_off);
    cudaGetSymbolAddress((void**)&awl,   g_awl);
    cudaGetSymbolAddress((void**)&val,   g_value);
    cudaGetSymbolAddress((void**)&cain,  g_cain);
    cudaGetSymbolAddress((void**)&caout, g_caout);
    cudaGetSymbolAddress((void**)&tgt3,  g_tgt3);
    cudaGetSymbolAddress((void**)&f1,    g_f1);
    cudaGetSymbolAddress((void**)&f2,    g_f2);

    // 1) q = tgt + query_mask
    add_kernel<<<TOKF/256, 256>>>(tgt, qmask, qbuf, TOKF);

    // 2) QKV projections, written directly in [b][h][q][d]
    launch_gemm(2, qbuf, DIM, 0, in_proj_w,           in_proj_b,       qh, 0, 0, NTOK, DIM, DIM, 1, nullptr, 0);
    launch_gemm(2, qbuf, DIM, 0, in_proj_w + 256*256, in_proj_b + 256, kh, 0, 0, NTOK, DIM, DIM, 1, nullptr, 0);
    launch_gemm(2, tgt,  DIM, 0, in_proj_w + 512*256, in_proj_b + 512, vh, 0, 0, NTOK, DIM, DIM, 1, nullptr, 0);

    // 3) fused self-attention
    {
        int smem = (300*36*2 + 150*32 + 8*320) * 4;   // 115,840 B
        cudaFuncSetAttribute(attn_kernel, cudaFuncAttributeMaxDynamicSharedMemorySize, smem);
        attn_kernel<<<128, 256, smem>>>(qh, kh, vh, sain);
    }

    // 4) self-attn out-proj + residual LN (norm2)
    launch_gemm(0, sain, DIM, 0, out_sa_w, out_sa_b, saout, DIM, 0, NTOK, DIM, DIM, 1, nullptr, 0);
    ln_kernel<<<NTOK/8, 256>>>(tgt, saout, 0, norm2_g, norm2_b, tgt2);

    // 5) query2 = (tgt2 + mask) in (b,q,d) layout
    permadd_kernel<<<TOKF/256, 256>>>(tgt2, qmask, q2);

    // 6) offsets + attention-weight logits
    launch_gemm(0, q2, DIM, 0, off_w, off_b, offb, 512, 0, NTOK, 512, DIM, 1, nullptr, 0);
    launch_gemm(0, q2, DIM, 0, aw_w,  aw_b,  awl,  DIM, 0, NTOK, DIM, DIM, 1, nullptr, 0);

    // 7) value projection over memory (batched: z = batch), pad-mask epilogue
    launch_gemm(3, memory, BSZ*DIM, DIM, value_w, value_b,
                val, DIM, (long)STOT*DIM, STOT, DIM, DIM, BSZ, pmask, STOT);

    // 8) deformable sampling
    deform_kernel<<<NTOK, 256>>>(offb, awl, bbox, val, spatial, lstart, cain);

    // 9) cross-attn out-proj + residual LN (norm1)
    launch_gemm(0, cain, DIM, 0, out_ca_w, out_ca_b, caout, DIM, 0, NTOK, DIM, DIM, 1, nullptr, 0);
    ln_kernel<<<NTOK/8, 256>>>(tgt2, caout, 1, norm1_g, norm1_b, tgt3);

    // 10) FFN + final LN (norm3) -> d_out
    launch_gemm(1, tgt3, DIM, 0, lin1_w, lin1_b, f1, DFF, 0, NTOK, DFF, DIM, 1, nullptr, 0);
    launch_gemm(0, f1,   DFF, 0, lin2_w, lin2_b, f2, DIM, 0, NTOK, DIM, DFF, 1, nullptr, 0);
    ln_kernel<<<NTOK/8, 256>>>(tgt3, f2, 0, norm3_g, norm3_b, out);
}

// round 3
// speedup vs baseline: 1.5649x; 1.5649x over previous
#include <cuda_runtime.h>
#include <cuda_bf16.h>
#include <math.h>
#include <cstdint>

// ---------------- problem constants ----------------
#define NQ   300
#define BSZ  8
#define DIM  256
#define NH   8
#define DH   32
#define DFF  1024
#define STOT 13294
#define NTOK (NQ*BSZ)          // 2400
#define TOKF (NTOK*DIM)        // 614400

// ---------------- scratch (static device globals; no allocations) ----------------
__device__ float g_qbuf [TOKF];
__device__ float g_qh   [TOKF];
__device__ float g_kh   [TOKF];
__device__ float g_vh   [TOKF];
__device__ float g_sain [TOKF];
__device__ float g_saout[TOKF];
__device__ float g_tgt2 [TOKF];
__device__ float g_q2   [TOKF];
__device__ float g_off  [NTOK*512];
__device__ float g_awl  [TOKF];
__device__ float g_value[(long)BSZ*STOT*DIM];
__device__ float g_cain [TOKF];
__device__ float g_caout[TOKF];
__device__ float g_tgt3 [TOKF];
__device__ float g_f1   [NTOK*DFF];
__device__ float g_f2   [TOKF];

// ---------------- helpers ----------------
__device__ __forceinline__ uint32_t smem_u32(const void* p) {
    uint32_t a;
    asm("{ .reg .u64 t; cvta.to.shared.u64 t, %1; cvt.u32.u64 %0, t; }" : "=r"(a) : "l"(p));
    return a;
}
__device__ __forceinline__ unsigned pk2(__nv_bfloat16 a, __nv_bfloat16 b) {
    __nv_bfloat162 t = __halves2bfloat162(a, b);
    return *reinterpret_cast<unsigned*>(&t);
}
__device__ __forceinline__ void mma_bf16(float* d, const uint32_t* a, uint32_t b0, uint32_t b1) {
    asm volatile(
        "mma.sync.aligned.m16n8k16.row.col.f32.bf16.bf16.f32 "
        "{%0,%1,%2,%3}, {%4,%5,%6,%7}, {%8,%9}, {%0,%1,%2,%3};"
        : "+f"(d[0]), "+f"(d[1]), "+f"(d[2]), "+f"(d[3])
        : "r"(a[0]), "r"(a[1]), "r"(a[2]), "r"(a[3]), "r"(b0), "r"(b1));
}
__device__ __forceinline__ void ldmx4(uint32_t* r, uint32_t addr) {
    asm volatile("ldmatrix.sync.aligned.m8n8.x4.shared.b16 {%0,%1,%2,%3}, [%4];"
                 : "=r"(r[0]), "=r"(r[1]), "=r"(r[2]), "=r"(r[3]) : "r"(addr));
}

// ============ mma.sync bf16 3-term GEMM: C = A(MxK)*W(NxK)^T + bias ============
// CTA 128x128, 512 thr, 16 warps of 32x32. K chunks of 32.
// smem rows of 64B (32 bf16), 16B chunks swizzled: c' = c ^ ((row>>1)&3).
// EPI: 0 plain, 1 relu, 2 QKV head-permute, 3 pad-mask zero
#define SA_HI 0
#define SA_LO 8192
#define SB_HI 16384
#define SB_LO 24576

template<int EPI>
__global__ void __launch_bounds__(512) mma_gemm(
    const float* __restrict__ A, int lda, long aOff,
    const float* __restrict__ W, int ldw,
    const float* __restrict__ bias,
    float* __restrict__ C, int ldc, long cOff,
    int M, int K,
    const unsigned char* __restrict__ mask, long mOff)
{
    __shared__ __align__(128) unsigned char sm[32768];
    const uint32_t sb = smem_u32(sm);
    const int tid = threadIdx.x;
    const int bm = blockIdx.y * 128;
    const int bn = blockIdx.x * 128;
    A += (long)blockIdx.z * aOff;
    C += (long)blockIdx.z * cOff;

    const int warp = tid >> 5, lane = tid & 31;
    const int wm = warp & 3, wn = warp >> 2;

    // prefetch-lane geometry: 1024 float4 per 128x32 tile, 2 per thread
    int prow[2], pkq[2];
    bool agd[2];
#pragma unroll
    for (int j = 0; j < 2; j++) {
        int i = tid + j * 512;
        prow[j] = i >> 3;
        pkq[j]  = i & 7;
        agd[j]  = (bm + prow[j]) < M;
    }

    float acc[2][4][4];
#pragma unroll
    for (int mt = 0; mt < 2; mt++)
#pragma unroll
        for (int nt = 0; nt < 4; nt++)
#pragma unroll
            for (int r = 0; r < 4; r++) acc[mt][nt][r] = 0.f;

    const int nk = K >> 5;
    float4 av[2], bv[2];

    // preload chunk 0
#pragma unroll
    for (int j = 0; j < 2; j++) {
        av[j] = agd[j] ? *(const float4*)(A + (long)(bm + prow[j]) * lda + pkq[j] * 4)
                       : make_float4(0.f, 0.f, 0.f, 0.f);
        bv[j] = *(const float4*)(W + (long)(bn + prow[j]) * ldw + pkq[j] * 4);
    }

    for (int kc = 0; kc < nk; kc++) {
        __syncthreads();   // previous compute done reading smem
        // convert + store to smem
#pragma unroll
        for (int j = 0; j < 2; j++) {
            int row = prow[j], kq = pkq[j];
            int c = kq >> 1;
            uint32_t off = (uint32_t)(row * 64 + (((c ^ ((row >> 1) & 3)) << 4)) + (kq & 1) * 8);
            {
                float4 v = av[j];
                __nv_bfloat16 h0 = __float2bfloat16_rn(v.x), h1 = __float2bfloat16_rn(v.y);
                __nv_bfloat16 h2 = __float2bfloat16_rn(v.z), h3 = __float2bfloat16_rn(v.w);
                __nv_bfloat16 l0 = __float2bfloat16_rn(v.x - __bfloat162float(h0));
                __nv_bfloat16 l1 = __float2bfloat16_rn(v.y - __bfloat162float(h1));
                __nv_bfloat16 l2 = __float2bfloat16_rn(v.z - __bfloat162float(h2));
                __nv_bfloat16 l3 = __float2bfloat16_rn(v.w - __bfloat162float(h3));
                *(uint2*)(sm + SA_HI + off) = make_uint2(pk2(h0, h1), pk2(h2, h3));
                *(uint2*)(sm + SA_LO + off) = make_uint2(pk2(l0, l1), pk2(l2, l3));
            }
            {
                float4 v = bv[j];
                __nv_bfloat16 h0 = __float2bfloat16_rn(v.x), h1 = __float2bfloat16_rn(v.y);
                __nv_bfloat16 h2 = __float2bfloat16_rn(v.z), h3 = __float2bfloat16_rn(v.w);
                __nv_bfloat16 l0 = __float2bfloat16_rn(v.x - __bfloat162float(h0));
                __nv_bfloat16 l1 = __float2bfloat16_rn(v.y - __bfloat162float(h1));
                __nv_bfloat16 l2 = __float2bfloat16_rn(v.z - __bfloat162float(h2));
                __nv_bfloat16 l3 = __float2bfloat16_rn(v.w - __bfloat162float(h3));
                *(uint2*)(sm + SB_HI + off) = make_uint2(pk2(h0, h1), pk2(h2, h3));
                *(uint2*)(sm + SB_LO + off) = make_uint2(pk2(l0, l1), pk2(l2, l3));
            }
        }
        __syncthreads();

        // prefetch next chunk while computing
        if (kc + 1 < nk) {
            int kb = (kc + 1) * 32;
#pragma unroll
            for (int j = 0; j < 2; j++) {
                av[j] = agd[j] ? *(const float4*)(A + (long)(bm + prow[j]) * lda + kb + pkq[j] * 4)
                               : make_float4(0.f, 0.f, 0.f, 0.f);
                bv[j] = *(const float4*)(W + (long)(bn + prow[j]) * ldw + kb + pkq[j] * 4);
            }
        }

        // compute: 2 k16 steps
#pragma unroll
        for (int ks = 0; ks < 2; ks++) {
            uint32_t ahi[2][4], alo[2][4];
#pragma unroll
            for (int mt = 0; mt < 2; mt++) {
                int row = wm * 32 + mt * 16 + (lane & 7) + ((lane >> 3) & 1) * 8;
                int c = 2 * ks + (lane >> 4);
                uint32_t off = (uint32_t)(row * 64 + ((c ^ ((row >> 1) & 3)) << 4));
                ldmx4(ahi[mt], sb + SA_HI + off);
                ldmx4(alo[mt], sb + SA_LO + off);
            }
            uint32_t bhi[4][2], blo[4][2];
#pragma unroll
            for (int np = 0; np < 2; np++) {
                int row = wn * 32 + np * 16 + (lane & 7) + (lane >> 4) * 8;
                int c = 2 * ks + ((lane >> 3) & 1);
                uint32_t off = (uint32_t)(row * 64 + ((c ^ ((row >> 1) & 3)) << 4));
                uint32_t t[4];
                ldmx4(t, sb + SB_HI + off);
                bhi[2*np][0] = t[0]; bhi[2*np][1] = t[1];
                bhi[2*np+1][0] = t[2]; bhi[2*np+1][1] = t[3];
                ldmx4(t, sb + SB_LO + off);
                blo[2*np][0] = t[0]; blo[2*np][1] = t[1];
                blo[2*np+1][0] = t[2]; blo[2*np+1][1] = t[3];
            }
#pragma unroll
            for (int mt = 0; mt < 2; mt++)
#pragma unroll
                for (int nt = 0; nt < 4; nt++) {
                    mma_bf16(acc[mt][nt], ahi[mt], bhi[nt][0], bhi[nt][1]);
                    mma_bf16(acc[mt][nt], ahi[mt], blo[nt][0], blo[nt][1]);
                    mma_bf16(acc[mt][nt], alo[mt], bhi[nt][0], bhi[nt][1]);
                }
        }
    }

    // ---------------- epilogue ----------------
#pragma unroll
    for (int mt = 0; mt < 2; mt++) {
        int r0 = bm + wm * 32 + mt * 16 + (lane >> 2);
#pragma unroll
        for (int nt = 0; nt < 4; nt++) {
            int n0 = bn + wn * 32 + nt * 8 + (lane & 3) * 2;
            float b0 = bias[n0], b1 = bias[n0 + 1];
#pragma unroll
            for (int half = 0; half < 2; half++) {
                int r = r0 + half * 8;
                if (r >= M) continue;
                float v0 = acc[mt][nt][half * 2 + 0] + b0;
                float v1 = acc[mt][nt][half * 2 + 1] + b1;
                if (EPI == 1) { v0 = fmaxf(v0, 0.f); v1 = fmaxf(v1, 0.f); }
                if (EPI == 3) {
                    if (mask[(long)blockIdx.z * mOff + r]) { v0 = 0.f; v1 = 0.f; }
                }
                if (EPI == 2) {
                    int q = r >> 3, bb = r & 7, hh = n0 >> 5, d = n0 & 31;
                    float* p = C + (((long)(bb * NH + hh)) * NQ + q) * DH + d;
                    p[0] = v0; p[1] = v1;
                } else {
                    float* p = C + (long)r * ldc + n0;
                    p[0] = v0; p[1] = v1;
                }
            }
        }
    }
}

static inline void launch_mma(int epi,
    const float* A, int lda, long aOff,
    const float* W, int ldw, const float* bias,
    float* C, int ldc, long cOff,
    int M, int N, int K, int nz,
    const unsigned char* mask, long mOff)
{
    dim3 grid(N / 128, (M + 127) / 128, nz);
    switch (epi) {
        case 0: mma_gemm<0><<<grid,512>>>(A,lda,aOff,W,ldw,bias,C,ldc,cOff,M,K,mask,mOff); break;
        case 1: mma_gemm<1><<<grid,512>>>(A,lda,aOff,W,ldw,bias,C,ldc,cOff,M,K,mask,mOff); break;
        case 2: mma_gemm<2><<<grid,512>>>(A,lda,aOff,W,ldw,bias,C,ldc,cOff,M,K,mask,mOff); break;
        case 3: mma_gemm<3><<<grid,512>>>(A,lda,aOff,W,ldw,bias,C,ldc,cOff,M,K,mask,mOff); break;
    }
}

// ---------------- elementwise ----------------
__global__ void add_kernel(const float* __restrict__ a, const float* __restrict__ b,
                           float* __restrict__ o, int n)
{
    int i = blockIdx.x * blockDim.x + threadIdx.x;
    if (i < n) o[i] = a[i] + b[i];
}

__global__ void permadd_kernel(const float* __restrict__ t2, const float* __restrict__ msk,
                               float* __restrict__ q2)
{
    int i = blockIdx.x * 256 + threadIdx.x;
    if (i >= TOKF) return;
    int d = i & 255;
    int t = i >> 8;
    int q = t >> 3, b = t & 7;
    q2[((long)(b*NQ + q) << 8) + d] = t2[i] + msk[i];
}

// ---------------- residual + layernorm ----------------
__global__ void __launch_bounds__(256) ln_kernel(
    const float* __restrict__ A, const float* __restrict__ B, int bBQ,
    const float* __restrict__ g, const float* __restrict__ be,
    float* __restrict__ out)
{
    int t = blockIdx.x * 8 + (threadIdx.x >> 5);
    int lane = threadIdx.x & 31;
    if (t >= NTOK) return;
    const float* ap = A + (long)t * DIM + lane*8;
    long bo;
    if (bBQ) { int q = t >> 3, b = t & 7; bo = (long)(b*NQ + q) * DIM; }
    else     { bo = (long)t * DIM; }
    const float* bp = B + bo + lane*8;

    float4 x0 = *(const float4*)ap,      x1 = *(const float4*)(ap + 4);
    float4 y0 = *(const float4*)bp,      y1 = *(const float4*)(bp + 4);
    float v[8] = {x0.x+y0.x, x0.y+y0.y, x0.z+y0.z, x0.w+y0.w,
                  x1.x+y1.x, x1.y+y1.y, x1.z+y1.z, x1.w+y1.w};
    float s = 0.f;
#pragma unroll
    for (int i = 0; i < 8; i++) s += v[i];
#pragma unroll
    for (int o = 16; o; o >>= 1) s += __shfl_xor_sync(0xffffffffu, s, o);
    float mu = s * (1.f/256.f);
    float s2 = 0.f;
#pragma unroll
    for (int i = 0; i < 8; i++) { float d = v[i] - mu; s2 += d*d; }
#pragma unroll
    for (int o = 16; o; o >>= 1) s2 += __shfl_xor_sync(0xffffffffu, s2, o);
    float inv = rsqrtf(s2 * (1.f/256.f) + 1e-5f);
    int c0 = lane*8;
    float* op = out + (long)t * DIM + c0;
#pragma unroll
    for (int i = 0; i < 8; i++)
        op[i] = (v[i] - mu) * inv * g[c0+i] + be[c0+i];
}

// ---------------- fused self-attention ----------------
__global__ void __launch_bounds__(256) attn_kernel(
    const float* __restrict__ qh, const float* __restrict__ kh,
    const float* __restrict__ vh, float* __restrict__ sa_in)
{
    extern __shared__ float smf[];
    const int bh   = blockIdx.x >> 1;
    const int half = blockIdx.x & 1;
    const int b = bh >> 3, h = bh & 7;
    float* Ks = smf;
    float* Vs = Ks + 300*36;
    float* Qs = Vs + 300*36;
    float* Ps = Qs + 150*32;

    const float scale = 0.17677669529663687f;
    const float* Kg = kh + (long)bh * NQ * DH;
    const float* Vg = vh + (long)bh * NQ * DH;
    const float* Qg = qh + (long)bh * NQ * DH + (long)half * 150 * DH;
    const int tid = threadIdx.x;

    for (int i = tid; i < 2400; i += 256) {
        int r = i >> 3, c4 = (i & 7) << 2;
        float4 kv = *(const float4*)(Kg + r*32 + c4);
        float4 vv = *(const float4*)(Vg + r*32 + c4);
        *(float4*)(Ks + r*36 + c4) = kv;
        *(float4*)(Vs + r*36 + c4) = vv;
    }
    for (int i = tid; i < 1200; i += 256) {
        int r = i >> 3, c4 = (i & 7) << 2;
        float4 qv = *(const float4*)(Qg + r*32 + c4);
        qv.x *= scale; qv.y *= scale; qv.z *= scale; qv.w *= scale;
        *(float4*)(Qs + r*32 + c4) = qv;
    }
    __syncthreads();

    const int warp = tid >> 5, lane = tid & 31;
    float* Pw = Ps + warp * 320;

    for (int q = warp; q < 150; q += 8) {
        float4 qr[8];
#pragma unroll
        for (int d4 = 0; d4 < 8; d4++) qr[d4] = *(const float4*)(Qs + q*32 + d4*4);

        float sc[10];
#pragma unroll
        for (int j = 0; j < 10; j++) {
            int k = j*32 + lane;
            float s = -1e30f;
            if (k < 300) {
                s = 0.f;
#pragma unroll
                for (int d4 = 0; d4 < 8; d4++) {
                    float4 kv = *(const float4*)(Ks + k*36 + d4*4);
                    s = fmaf(qr[d4].x, kv.x, s);
                    s = fmaf(qr[d4].y, kv.y, s);
                    s = fmaf(qr[d4].z, kv.z, s);
                    s = fmaf(qr[d4].w, kv.w, s);
                }
            }
            sc[j] = s;
        }
        float m = sc[0];
#pragma unroll
        for (int j = 1; j < 10; j++) m = fmaxf(m, sc[j]);
#pragma unroll
        for (int o = 16; o; o >>= 1) m = fmaxf(m, __shfl_xor_sync(0xffffffffu, m, o));
        float sum = 0.f;
#pragma unroll
        for (int j = 0; j < 10; j++) { sc[j] = expf(sc[j] - m); sum += sc[j]; }
#pragma unroll
        for (int o = 16; o; o >>= 1) sum += __shfl_xor_sync(0xffffffffu, sum, o);
        float inv = 1.f / sum;
#pragma unroll
        for (int j = 0; j < 10; j++) Pw[j*32 + lane] = sc[j] * inv;
        __syncwarp();

        float acc = 0.f;
#pragma unroll 4
        for (int k = 0; k < 300; k++)
            acc = fmaf(Pw[k], Vs[k*36 + lane], acc);

        int qg = half*150 + q;
        sa_in[((long)(qg*BSZ + b)) * DIM + h*DH + lane] = acc;
        __syncwarp();
    }
}

// ---------------- multi-scale deformable sampling ----------------
__global__ void __launch_bounds__(256) deform_kernel(
    const float* __restrict__ offp, const float* __restrict__ awl,
    const float* __restrict__ bbox, const float* __restrict__ value,
    const int* __restrict__ spatial, const int* __restrict__ lstart,
    float* __restrict__ ca_in)
{
    __shared__ float s_w[8][32][4];
    __shared__ int   s_i[8][32][4];
    int bq = blockIdx.x;
    int b = bq / NQ, q = bq - b*NQ;
    int warp = threadIdx.x >> 5, lane = threadIdx.x & 31;

    float a = awl[(long)bq*256 + warp*32 + lane];
    float m = a;
#pragma unroll
    for (int o = 16; o; o >>= 1) m = fmaxf(m, __shfl_xor_sync(0xffffffffu, m, o));
    float e = expf(a - m);
    float s = e;
#pragma unroll
    for (int o = 16; o; o >>= 1) s += __shfl_xor_sync(0xffffffffu, s, o);
    float p = e / s;

    float ox = offp[(long)bq*512 + warp*64 + lane*2];
    float oy = offp[(long)bq*512 + warp*64 + lane*2 + 1];
    const float* rb = bbox + ((long)q*BSZ + b)*4;
    float r0 = rb[0], r1 = rb[1], r2 = rb[2], r3 = rb[3];

    int lvl = lane >> 3;
    int H = spatial[lvl*2], W = spatial[lvl*2 + 1], ls = lstart[lvl];
    float Wf = (float)W, Hf = (float)H;
    float x = (r0 + ox*0.0625f*r2) * Wf - 0.5f;
    float y = (r1 + oy*0.0625f*r3) * Hf - 0.5f;
    float x0 = floorf(x), y0 = floorf(y);
    float fx = x - x0, fy = y - y0;

#pragma unroll
    for (int c = 0; c < 4; c++) {
        float xi = x0 + (float)(c & 1);
        float yi = y0 + (float)(c >> 1);
        float wgt = ((c & 1) ? fx : 1.f - fx) * ((c >> 1) ? fy : 1.f - fy);
        bool valid = (xi >= 0.f) && (xi < Wf) && (yi >= 0.f) && (yi < Hf);
        int xc = (int)fminf(fmaxf(xi, 0.f), Wf - 1.f);
        int yc = (int)fminf(fmaxf(yi, 0.f), Hf - 1.f);
        s_i[warp][lane][c] = ls + yc*W + xc;
        s_w[warp][lane][c] = valid ? wgt * p : 0.f;
    }
    __syncwarp();

    const float* vb = value + (long)b * STOT * DIM + warp*DH + lane;
    float acc = 0.f;
    for (int lp = 0; lp < 32; lp++) {
#pragma unroll
        for (int c = 0; c < 4; c++) {
            float wgt = s_w[warp][lp][c];
            if (wgt != 0.f)
                acc = fmaf(wgt, vb[(long)s_i[warp][lp][c] << 8], acc);
        }
    }
    ca_in[(long)bq*DIM + warp*DH + lane] = acc;
}

// ---------------- host orchestration ----------------
extern "C" void kernel_launch(void* const* d_in, const int* in_sizes, int n_in,
                              void* d_out, int out_size)
{
    const float* tgt        = (const float*)d_in[0];
    const float* qmask      = (const float*)d_in[1];
    const float* bbox       = (const float*)d_in[2];
    const float* memory     = (const float*)d_in[4];
    const float* in_proj_w  = (const float*)d_in[5];
    const float* in_proj_b  = (const float*)d_in[6];
    const float* out_sa_w   = (const float*)d_in[7];
    const float* out_sa_b   = (const float*)d_in[8];
    const float* norm2_g    = (const float*)d_in[9];
    const float* norm2_b    = (const float*)d_in[10];
    const float* value_w    = (const float*)d_in[11];
    const float* value_b    = (const float*)d_in[12];
    const float* off_w      = (const float*)d_in[13];
    const float* off_b      = (const float*)d_in[14];
    const float* aw_w       = (const float*)d_in[15];
    const float* aw_b       = (const float*)d_in[16];
    const float* out_ca_w   = (const float*)d_in[17];
    const float* out_ca_b   = (const float*)d_in[18];
    const float* norm1_g    = (const float*)d_in[19];
    const float* norm1_b    = (const float*)d_in[20];
    const float* lin1_w     = (const float*)d_in[21];
    const float* lin1_b     = (const float*)d_in[22];
    const float* lin2_w     = (const float*)d_in[23];
    const float* lin2_b     = (const float*)d_in[24];
    const float* norm3_g    = (const float*)d_in[25];
    const float* norm3_b    = (const float*)d_in[26];
    const unsigned char* pmask = (const unsigned char*)d_in[27];
    const int* spatial      = (const int*)d_in[28];
    const int* lstart       = (const int*)d_in[29];
    float* out = (float*)d_out;

    float *qbuf,*qh,*kh,*vh,*sain,*saout,*tgt2,*q2,*offb,*awl,*val,*cain,*caout,*tgt3,*f1,*f2;
    cudaGetSymbolAddress((void**)&qbuf,  g_qbuf);
    cudaGetSymbolAddress((void**)&qh,    g_qh);
    cudaGetSymbolAddress((void**)&kh,    g_kh);
    cudaGetSymbolAddress((void**)&vh,    g_vh);
    cudaGetSymbolAddress((void**)&sain,  g_sain);
    cudaGetSymbolAddress((void**)&saout, g_saout);
    cudaGetSymbolAddress((void**)&tgt2,  g_tgt2);
    cudaGetSymbolAddress((void**)&q2,    g_q2);
    cudaGetSymbolAddress((void**)&offb,  g_off);
    cudaGetSymbolAddress((void**)&awl,   g_awl);
    cudaGetSymbolAddress((void**)&val,   g_value);
    cudaGetSymbolAddress((void**)&cain,  g_cain);
    cudaGetSymbolAddress((void**)&caout, g_caout);
    cudaGetSymbolAddress((void**)&tgt3,  g_tgt3);
    cudaGetSymbolAddress((void**)&f1,    g_f1);
    cudaGetSymbolAddress((void**)&f2,    g_f2);

    // 1) q = tgt + query_mask
    add_kernel<<<TOKF/256, 256>>>(tgt, qmask, qbuf, TOKF);

    // 2) value projection over memory (batched over BS): biggest GEMM
    launch_mma(3, memory, BSZ*DIM, 256, value_w, DIM, value_b,
               val, DIM, (long)STOT*DIM, STOT, DIM, DIM, BSZ, pmask, STOT);

    // 3) QKV projections -> [b][h][q][d]
    launch_mma(2, qbuf, DIM, 0, in_proj_w,           DIM, in_proj_b,       qh, 0, 0, NTOK, DIM, DIM, 1, nullptr, 0);
    launch_mma(2, qbuf, DIM, 0, in_proj_w + 256*256, DIM, in_proj_b + 256, kh, 0, 0, NTOK, DIM, DIM, 1, nullptr, 0);
    launch_mma(2, tgt,  DIM, 0, in_proj_w + 512*256, DIM, in_proj_b + 512, vh, 0, 0, NTOK, DIM, DIM, 1, nullptr, 0);

    // 4) fused self-attention
    {
        int smem = (300*36*2 + 150*32 + 8*320) * 4;
        cudaFuncSetAttribute(attn_kernel, cudaFuncAttributeMaxDynamicSharedMemorySize, smem);
        attn_kernel<<<128, 256, smem>>>(qh, kh, vh, sain);
    }

    // 5) self-attn out-proj + residual LN (norm2)
    launch_mma(0, sain, DIM, 0, out_sa_w, DIM, out_sa_b, saout, DIM, 0, NTOK, DIM, DIM, 1, nullptr, 0);
    ln_kernel<<<NTOK/8, 256>>>(tgt, saout, 0, norm2_g, norm2_b, tgt2);

    // 6) query2 = (tgt2 + mask) in (b,q,d) layout
    permadd_kernel<<<TOKF/256, 256>>>(tgt2, qmask, q2);

    // 7) offsets + attention-weight logits
    launch_mma(0, q2, DIM, 0, off_w, DIM, off_b, offb, 512, 0, NTOK, 512, DIM, 1, nullptr, 0);
    launch_mma(0, q2, DIM, 0, aw_w,  DIM, aw_b,  awl,  DIM, 0, NTOK, DIM, DIM, 1, nullptr, 0);

    // 8) deformable sampling
    deform_kernel<<<NTOK, 256>>>(offb, awl, bbox, val, spatial, lstart, cain);

    // 9) cross-attn out-proj + residual LN (norm1)
    launch_mma(0, cain, DIM, 0, out_ca_w, DIM, out_ca_b, caout, DIM, 0, NTOK, DIM, DIM, 1, nullptr, 0);
    ln_kernel<<<NTOK/8, 256>>>(tgt2, caout, 1, norm1_g, norm1_b, tgt3);

    // 10) FFN + final LN (norm3) -> d_out
    launch_mma(1, tgt3, DIM, 0, lin1_w, DIM, lin1_b, f1, DFF, 0, NTOK, DFF, DIM, 1, nullptr, 0);
    launch_mma(0, f1,   DFF, 0, lin2_w, DFF, lin2_b, f2, DIM, 0, NTOK, DIM, DFF, 1, nullptr, 0);
    ln_kernel<<<NTOK/8, 256>>>(tgt3, f2, 0, norm3_g, norm3_b, out);
}

// round 4
// speedup vs baseline: 1.8799x; 1.2013x over previous
#include <cuda_runtime.h>
#include <cuda_bf16.h>
#include <math.h>
#include <cstdint>

// ---------------- problem constants ----------------
#define NQ   300
#define BSZ  8
#define DIM  256
#define NH   8
#define DH   32
#define DFF  1024
#define STOT 13294
#define NTOK (NQ*BSZ)          // 2400
#define TOKF (NTOK*DIM)        // 614400

// ---------------- scratch (static device globals; no allocations) ----------------
__device__ float g_qbuf [TOKF];
__device__ float g_qh   [TOKF];
__device__ float g_kh   [TOKF];
__device__ float g_vh   [TOKF];
__device__ float g_sain [TOKF];
__device__ float g_saout[TOKF];
__device__ float g_tgt2 [TOKF];
__device__ float g_q2   [TOKF];
__device__ float g_off  [NTOK*768];          // off (512) + aw logits (256) per token
__device__ float g_value[(long)BSZ*STOT*DIM];
__device__ float g_cain [TOKF];
__device__ float g_caout[TOKF];
__device__ float g_tgt3 [TOKF];
__device__ float g_f1   [NTOK*DFF];
__device__ float g_f2   [TOKF];

// ---------------- helpers ----------------
__device__ __forceinline__ uint32_t smem_u32(const void* p) {
    uint32_t a;
    asm("{ .reg .u64 t; cvta.to.shared.u64 t, %1; cvt.u32.u64 %0, t; }" : "=r"(a) : "l"(p));
    return a;
}
__device__ __forceinline__ unsigned pk2(__nv_bfloat16 a, __nv_bfloat16 b) {
    __nv_bfloat162 t = __halves2bfloat162(a, b);
    return *reinterpret_cast<unsigned*>(&t);
}
__device__ __forceinline__ void mma_bf16(float* d, const uint32_t* a, uint32_t b0, uint32_t b1) {
    asm volatile(
        "mma.sync.aligned.m16n8k16.row.col.f32.bf16.bf16.f32 "
        "{%0,%1,%2,%3}, {%4,%5,%6,%7}, {%8,%9}, {%0,%1,%2,%3};"
        : "+f"(d[0]), "+f"(d[1]), "+f"(d[2]), "+f"(d[3])
        : "r"(a[0]), "r"(a[1]), "r"(a[2]), "r"(a[3]), "r"(b0), "r"(b1));
}
__device__ __forceinline__ void ldmx4(uint32_t* r, uint32_t addr) {
    asm volatile("ldmatrix.sync.aligned.m8n8.x4.shared.b16 {%0,%1,%2,%3}, [%4];"
                 : "=r"(r[0]), "=r"(r[1]), "=r"(r[2]), "=r"(r[3]) : "r"(addr));
}
__device__ __forceinline__ void cvt_hilo(float4 v, uint2& hi, uint2& lo) {
    __nv_bfloat16 h0 = __float2bfloat16_rn(v.x), h1 = __float2bfloat16_rn(v.y);
    __nv_bfloat16 h2 = __float2bfloat16_rn(v.z), h3 = __float2bfloat16_rn(v.w);
    __nv_bfloat16 l0 = __float2bfloat16_rn(v.x - __bfloat162float(h0));
    __nv_bfloat16 l1 = __float2bfloat16_rn(v.y - __bfloat162float(h1));
    __nv_bfloat16 l2 = __float2bfloat16_rn(v.z - __bfloat162float(h2));
    __nv_bfloat16 l3 = __float2bfloat16_rn(v.w - __bfloat162float(h3));
    hi = make_uint2(pk2(h0, h1), pk2(h2, h3));
    lo = make_uint2(pk2(l0, l1), pk2(l2, l3));
}

// ============ mma.sync bf16 3-term GEMM: C = A(MxK)*W(NxK)^T + bias ============
// CTA 64x128, 256 thr, 8 warps of 32x32. K chunks of 32. 2-stage smem ping-pong.
// Stage layout (24576 B): A_hi[64x32] 0, A_lo 4096, B_hi[128x32] 8192, B_lo 16384.
// smem rows of 64B; 16B chunks swizzled: c' = c ^ ((row>>1)&3).
// EPI: 0 plain, 1 relu, 2 head-permute [(b*NH+h)][q][d] (C2 = second output for n>=256),
//      3 pad-mask zero. Nsplit: per-CTA W/bias switch to W2/bias2 at column Nsplit.
#define STG 24576

template<int EPI>
__global__ void __launch_bounds__(256, 2) mma_gemm(
    const float* __restrict__ A, int lda, long aOff,
    const float* __restrict__ W, int ldw,
    const float* __restrict__ bias,
    const float* __restrict__ W2, const float* __restrict__ bias2, int Nsplit,
    float* __restrict__ C, float* __restrict__ C2, int ldc, long cOff,
    int M, int K,
    const unsigned char* __restrict__ mask, long mOff)
{
    extern __shared__ __align__(128) unsigned char sm[];
    const uint32_t sb = smem_u32(sm);
    const int tid = threadIdx.x;
    const int bm = blockIdx.y * 64;
    const int bn = blockIdx.x * 128;
    A += (long)blockIdx.z * aOff;
    C += (long)blockIdx.z * cOff;
    if (Nsplit && bn >= Nsplit) { W = W2 - (long)Nsplit * ldw; bias = bias2 - Nsplit; }

    const int warp = tid >> 5, lane = tid & 31;
    const int wm = warp & 1, wn = warp >> 1;

    // prefetch geometry: A tile 64x32 = 512 float4 (2/thr), B tile 128x32 = 1024 (4/thr)
    int arow[2], akq[2]; bool agd[2]; const float* aptr[2];
#pragma unroll
    for (int j = 0; j < 2; j++) {
        int i = tid + j * 256;
        arow[j] = i >> 3; akq[j] = i & 7;
        agd[j] = (bm + arow[j]) < M;
        aptr[j] = A + (long)(bm + arow[j]) * lda + akq[j] * 4;
    }
    int brow[4], bkq[4]; const float* bptr[4];
#pragma unroll
    for (int j = 0; j < 4; j++) {
        int i = tid + j * 256;
        brow[j] = i >> 3; bkq[j] = i & 7;
        bptr[j] = W + (long)(bn + brow[j]) * ldw + bkq[j] * 4;
    }
    uint32_t asw[2], bsw[4];
#pragma unroll
    for (int j = 0; j < 2; j++)
        asw[j] = (uint32_t)(arow[j] * 64 + (((akq[j] >> 1) ^ ((arow[j] >> 1) & 3)) << 4) + (akq[j] & 1) * 8);
#pragma unroll
    for (int j = 0; j < 4; j++)
        bsw[j] = (uint32_t)(brow[j] * 64 + (((bkq[j] >> 1) ^ ((brow[j] >> 1) & 3)) << 4) + (bkq[j] & 1) * 8);

    float acc[2][4][4];
#pragma unroll
    for (int mt = 0; mt < 2; mt++)
#pragma unroll
        for (int nt = 0; nt < 4; nt++)
#pragma unroll
            for (int r = 0; r < 4; r++) acc[mt][nt][r] = 0.f;

    const int nk = K >> 5;
    float4 av[2], bv[4];

    // load + stage chunk 0
#pragma unroll
    for (int j = 0; j < 2; j++)
        av[j] = agd[j] ? *(const float4*)(aptr[j]) : make_float4(0.f,0.f,0.f,0.f);
#pragma unroll
    for (int j = 0; j < 4; j++) bv[j] = *(const float4*)(bptr[j]);
#pragma unroll
    for (int j = 0; j < 2; j++) {
        uint2 hi, lo; cvt_hilo(av[j], hi, lo);
        *(uint2*)(sm + asw[j]) = hi;
        *(uint2*)(sm + 4096 + asw[j]) = lo;
    }
#pragma unroll
    for (int j = 0; j < 4; j++) {
        uint2 hi, lo; cvt_hilo(bv[j], hi, lo);
        *(uint2*)(sm + 8192 + bsw[j]) = hi;
        *(uint2*)(sm + 16384 + bsw[j]) = lo;
    }
    __syncthreads();

    for (int kc = 0; kc < nk; kc++) {
        const int st = kc & 1;
        const uint32_t so = sb + (uint32_t)(st * STG);
        const bool more = (kc + 1) < nk;

        // issue gmem loads for next chunk first (latency overlapped with mma)
        if (more) {
            int kb = (kc + 1) * 32;
#pragma unroll
            for (int j = 0; j < 2; j++)
                av[j] = agd[j] ? *(const float4*)(aptr[j] + kb) : make_float4(0.f,0.f,0.f,0.f);
#pragma unroll
            for (int j = 0; j < 4; j++) bv[j] = *(const float4*)(bptr[j] + kb);
        }

        // compute on current stage: 2 k16 steps
#pragma unroll
        for (int ks = 0; ks < 2; ks++) {
            uint32_t ahi[2][4], alo[2][4];
#pragma unroll
            for (int mt = 0; mt < 2; mt++) {
                int row = wm * 32 + mt * 16 + (lane & 7) + ((lane >> 3) & 1) * 8;
                int c = 2 * ks + (lane >> 4);
                uint32_t off = (uint32_t)(row * 64 + ((c ^ ((row >> 1) & 3)) << 4));
                ldmx4(ahi[mt], so + off);
                ldmx4(alo[mt], so + 4096 + off);
            }
            uint32_t bhi[4][2], blo[4][2];
#pragma unroll
            for (int np = 0; np < 2; np++) {
                int row = wn * 32 + np * 16 + (lane & 7) + (lane >> 4) * 8;
                int c = 2 * ks + ((lane >> 3) & 1);
                uint32_t off = (uint32_t)(row * 64 + ((c ^ ((row >> 1) & 3)) << 4));
                uint32_t t[4];
                ldmx4(t, so + 8192 + off);
                bhi[2*np][0] = t[0]; bhi[2*np][1] = t[1];
                bhi[2*np+1][0] = t[2]; bhi[2*np+1][1] = t[3];
                ldmx4(t, so + 16384 + off);
                blo[2*np][0] = t[0]; blo[2*np][1] = t[1];
                blo[2*np+1][0] = t[2]; blo[2*np+1][1] = t[3];
            }
#pragma unroll
            for (int mt = 0; mt < 2; mt++)
#pragma unroll
                for (int nt = 0; nt < 4; nt++) {
                    mma_bf16(acc[mt][nt], ahi[mt], bhi[nt][0], bhi[nt][1]);
                    mma_bf16(acc[mt][nt], ahi[mt], blo[nt][0], blo[nt][1]);
                    mma_bf16(acc[mt][nt], alo[mt], bhi[nt][0], bhi[nt][1]);
                }
        }

        // convert + store next chunk into the other stage (safe: other buffer)
        if (more) {
            const uint32_t po = (uint32_t)((st ^ 1) * STG);
#pragma unroll
            for (int j = 0; j < 2; j++) {
                uint2 hi, lo; cvt_hilo(av[j], hi, lo);
                *(uint2*)(sm + po + asw[j]) = hi;
                *(uint2*)(sm + po + 4096 + asw[j]) = lo;
            }
#pragma unroll
            for (int j = 0; j < 4; j++) {
                uint2 hi, lo; cvt_hilo(bv[j], hi, lo);
                *(uint2*)(sm + po + 8192 + bsw[j]) = hi;
                *(uint2*)(sm + po + 16384 + bsw[j]) = lo;
            }
        }
        __syncthreads();
    }

    // ---------------- epilogue ----------------
#pragma unroll
    for (int mt = 0; mt < 2; mt++) {
        int r0 = bm + wm * 32 + mt * 16 + (lane >> 2);
#pragma unroll
        for (int nt = 0; nt < 4; nt++) {
            int n0 = bn + wn * 32 + nt * 8 + (lane & 3) * 2;
            float b0 = bias[n0], b1 = bias[n0 + 1];
#pragma unroll
            for (int half = 0; half < 2; half++) {
                int r = r0 + half * 8;
                if (r >= M) continue;
                float v0 = acc[mt][nt][half * 2 + 0] + b0;
                float v1 = acc[mt][nt][half * 2 + 1] + b1;
                if (EPI == 1) { v0 = fmaxf(v0, 0.f); v1 = fmaxf(v1, 0.f); }
                if (EPI == 3) {
                    if (mask[(long)blockIdx.z * mOff + r]) { v0 = 0.f; v1 = 0.f; }
                }
                if (EPI == 2) {
                    float* base = C; int nn = n0;
                    if (C2 && nn >= 256) { base = C2; nn -= 256; }
                    int q = r >> 3, bb = r & 7, hh = nn >> 5, d = nn & 31;
                    float* p = base + (((long)(bb * NH + hh)) * NQ + q) * DH + d;
                    p[0] = v0; p[1] = v1;
                } else {
                    float* p = C + (long)r * ldc + n0;
                    p[0] = v0; p[1] = v1;
                }
            }
        }
    }
}

static inline void launch_mma(int epi,
    const float* A, int lda, long aOff,
    const float* W, int ldw, const float* bias,
    const float* W2, const float* bias2, int Nsplit,
    float* C, float* C2, int ldc, long cOff,
    int M, int N, int K, int nz,
    const unsigned char* mask, long mOff)
{
    dim3 grid(N / 128, (M + 63) / 64, nz);
    const int SMEM = 2 * STG;
    switch (epi) {
        case 0:
            cudaFuncSetAttribute(mma_gemm<0>, cudaFuncAttributeMaxDynamicSharedMemorySize, SMEM);
            mma_gemm<0><<<grid,256,SMEM>>>(A,lda,aOff,W,ldw,bias,W2,bias2,Nsplit,C,C2,ldc,cOff,M,K,mask,mOff);
            break;
        case 1:
            cudaFuncSetAttribute(mma_gemm<1>, cudaFuncAttributeMaxDynamicSharedMemorySize, SMEM);
            mma_gemm<1><<<grid,256,SMEM>>>(A,lda,aOff,W,ldw,bias,W2,bias2,Nsplit,C,C2,ldc,cOff,M,K,mask,mOff);
            break;
        case 2:
            cudaFuncSetAttribute(mma_gemm<2>, cudaFuncAttributeMaxDynamicSharedMemorySize, SMEM);
            mma_gemm<2><<<grid,256,SMEM>>>(A,lda,aOff,W,ldw,bias,W2,bias2,Nsplit,C,C2,ldc,cOff,M,K,mask,mOff);
            break;
        case 3:
            cudaFuncSetAttribute(mma_gemm<3>, cudaFuncAttributeMaxDynamicSharedMemorySize, SMEM);
            mma_gemm<3><<<grid,256,SMEM>>>(A,lda,aOff,W,ldw,bias,W2,bias2,Nsplit,C,C2,ldc,cOff,M,K,mask,mOff);
            break;
    }
}

// ---------------- elementwise ----------------
__global__ void add_kernel(const float* __restrict__ a, const float* __restrict__ b,
                           float* __restrict__ o, int n4)
{
    int i = blockIdx.x * blockDim.x + threadIdx.x;
    if (i < n4) {
        float4 x = ((const float4*)a)[i], y = ((const float4*)b)[i];
        ((float4*)o)[i] = make_float4(x.x+y.x, x.y+y.y, x.z+y.z, x.w+y.w);
    }
}

__global__ void permadd_kernel(const float* __restrict__ t2, const float* __restrict__ msk,
                               float* __restrict__ q2)
{
    int i = blockIdx.x * 256 + threadIdx.x;   // over TOKF/4 float4s
    if (i >= TOKF/4) return;
    int d4 = i & 63;
    int t = i >> 6;
    int q = t >> 3, b = t & 7;
    float4 x = ((const float4*)t2)[i], y = ((const float4*)msk)[i];
    ((float4*)q2)[((long)(b*NQ + q) << 6) + d4] = make_float4(x.x+y.x, x.y+y.y, x.z+y.z, x.w+y.w);
}

// ---------------- residual + layernorm ----------------
__global__ void __launch_bounds__(256) ln_kernel(
    const float* __restrict__ A, const float* __restrict__ B, int bBQ,
    const float* __restrict__ g, const float* __restrict__ be,
    float* __restrict__ out)
{
    int t = blockIdx.x * 8 + (threadIdx.x >> 5);
    int lane = threadIdx.x & 31;
    if (t >= NTOK) return;
    const float* ap = A + (long)t * DIM + lane*8;
    long bo;
    if (bBQ) { int q = t >> 3, b = t & 7; bo = (long)(b*NQ + q) * DIM; }
    else     { bo = (long)t * DIM; }
    const float* bp = B + bo + lane*8;

    float4 x0 = *(const float4*)ap,      x1 = *(const float4*)(ap + 4);
    float4 y0 = *(const float4*)bp,      y1 = *(const float4*)(bp + 4);
    float v[8] = {x0.x+y0.x, x0.y+y0.y, x0.z+y0.z, x0.w+y0.w,
                  x1.x+y1.x, x1.y+y1.y, x1.z+y1.z, x1.w+y1.w};
    float s = 0.f;
#pragma unroll
    for (int i = 0; i < 8; i++) s += v[i];
#pragma unroll
    for (int o = 16; o; o >>= 1) s += __shfl_xor_sync(0xffffffffu, s, o);
    float mu = s * (1.f/256.f);
    float s2 = 0.f;
#pragma unroll
    for (int i = 0; i < 8; i++) { float d = v[i] - mu; s2 += d*d; }
#pragma unroll
    for (int o = 16; o; o >>= 1) s2 += __shfl_xor_sync(0xffffffffu, s2, o);
    float inv = rsqrtf(s2 * (1.f/256.f) + 1e-5f);
    int c0 = lane*8;
    float* op = out + (long)t * DIM + c0;
#pragma unroll
    for (int i = 0; i < 8; i++)
        op[i] = (v[i] - mu) * inv * g[c0+i] + be[c0+i];
}

// ---------------- fused self-attention ----------------
__global__ void __launch_bounds__(256) attn_kernel(
    const float* __restrict__ qh, const float* __restrict__ kh,
    const float* __restrict__ vh, float* __restrict__ sa_in)
{
    extern __shared__ float smf[];
    const int bh   = blockIdx.x >> 1;
    const int half = blockIdx.x & 1;
    const int b = bh >> 3, h = bh & 7;
    float* Ks = smf;
    float* Vs = Ks + 300*36;
    float* Qs = Vs + 300*36;
    float* Ps = Qs + 150*32;

    const float scale = 0.17677669529663687f;
    const float* Kg = kh + (long)bh * NQ * DH;
    const float* Vg = vh + (long)bh * NQ * DH;
    const float* Qg = qh + (long)bh * NQ * DH + (long)half * 150 * DH;
    const int tid = threadIdx.x;

    for (int i = tid; i < 2400; i += 256) {
        int r = i >> 3, c4 = (i & 7) << 2;
        float4 kv = *(const float4*)(Kg + r*32 + c4);
        float4 vv = *(const float4*)(Vg + r*32 + c4);
        *(float4*)(Ks + r*36 + c4) = kv;
        *(float4*)(Vs + r*36 + c4) = vv;
    }
    for (int i = tid; i < 1200; i += 256) {
        int r = i >> 3, c4 = (i & 7) << 2;
        float4 qv = *(const float4*)(Qg + r*32 + c4);
        qv.x *= scale; qv.y *= scale; qv.z *= scale; qv.w *= scale;
        *(float4*)(Qs + r*32 + c4) = qv;
    }
    __syncthreads();

    const int warp = tid >> 5, lane = tid & 31;
    float* Pw = Ps + warp * 320;

    for (int q = warp; q < 150; q += 8) {
        float4 qr[8];
#pragma unroll
        for (int d4 = 0; d4 < 8; d4++) qr[d4] = *(const float4*)(Qs + q*32 + d4*4);

        float sc[10];
#pragma unroll
        for (int j = 0; j < 10; j++) {
            int k = j*32 + lane;
            float s = -1e30f;
            if (k < 300) {
                s = 0.f;
#pragma unroll
                for (int d4 = 0; d4 < 8; d4++) {
                    float4 kv = *(const float4*)(Ks + k*36 + d4*4);
                    s = fmaf(qr[d4].x, kv.x, s);
                    s = fmaf(qr[d4].y, kv.y, s);
                    s = fmaf(qr[d4].z, kv.z, s);
                    s = fmaf(qr[d4].w, kv.w, s);
                }
            }
            sc[j] = s;
        }
        float m = sc[0];
#pragma unroll
        for (int j = 1; j < 10; j++) m = fmaxf(m, sc[j]);
#pragma unroll
        for (int o = 16; o; o >>= 1) m = fmaxf(m, __shfl_xor_sync(0xffffffffu, m, o));
        float sum = 0.f;
#pragma unroll
        for (int j = 0; j < 10; j++) { sc[j] = expf(sc[j] - m); sum += sc[j]; }
#pragma unroll
        for (int o = 16; o; o >>= 1) sum += __shfl_xor_sync(0xffffffffu, sum, o);
        float inv = 1.f / sum;
#pragma unroll
        for (int j = 0; j < 10; j++) Pw[j*32 + lane] = sc[j] * inv;
        __syncwarp();

        float acc = 0.f;
#pragma unroll 4
        for (int k = 0; k < 300; k++)
            acc = fmaf(Pw[k], Vs[k*36 + lane], acc);

        int qg = half*150 + q;
        sa_in[((long)(qg*BSZ + b)) * DIM + h*DH + lane] = acc;
        __syncwarp();
    }
}

// ---------------- multi-scale deformable sampling ----------------
// block per (b,q), warp per head. lane = (l,p). off/aw packed: 768 floats per token.
__global__ void __launch_bounds__(256) deform_kernel(
    const float* __restrict__ offaw,
    const float* __restrict__ bbox, const float* __restrict__ value,
    const int* __restrict__ spatial, const int* __restrict__ lstart,
    float* __restrict__ ca_in)
{
    __shared__ float s_w[8][32][4];
    __shared__ int   s_i[8][32][4];
    int bq = blockIdx.x;
    int b = bq / NQ, q = bq - b*NQ;
    int warp = threadIdx.x >> 5, lane = threadIdx.x & 31;

    const float* tok = offaw + (long)bq * 768;
    float a = tok[512 + warp*32 + lane];
    float m = a;
#pragma unroll
    for (int o = 16; o; o >>= 1) m = fmaxf(m, __shfl_xor_sync(0xffffffffu, m, o));
    float e = expf(a - m);
    float s = e;
#pragma unroll
    for (int o = 16; o; o >>= 1) s += __shfl_xor_sync(0xffffffffu, s, o);
    float p = e / s;

    float ox = tok[warp*64 + lane*2];
    float oy = tok[warp*64 + lane*2 + 1];
    const float* rb = bbox + ((long)q*BSZ + b)*4;
    float r0 = rb[0], r1 = rb[1], r2 = rb[2], r3 = rb[3];

    int lvl = lane >> 3;
    int H = spatial[lvl*2], W = spatial[lvl*2 + 1], ls = lstart[lvl];
    float Wf = (float)W, Hf = (float)H;
    float x = (r0 + ox*0.0625f*r2) * Wf - 0.5f;
    float y = (r1 + oy*0.0625f*r3) * Hf - 0.5f;
    float x0 = floorf(x), y0 = floorf(y);
    float fx = x - x0, fy = y - y0;

#pragma unroll
    for (int c = 0; c < 4; c++) {
        float xi = x0 + (float)(c & 1);
        float yi = y0 + (float)(c >> 1);
        float wgt = ((c & 1) ? fx : 1.f - fx) * ((c >> 1) ? fy : 1.f - fy);
        bool valid = (xi >= 0.f) && (xi < Wf) && (yi >= 0.f) && (yi < Hf);
        int xc = (int)fminf(fmaxf(xi, 0.f), Wf - 1.f);
        int yc = (int)fminf(fmaxf(yi, 0.f), Hf - 1.f);
        s_i[warp][lane][c] = ls + yc*W + xc;
        s_w[warp][lane][c] = valid ? wgt * p : 0.f;
    }
    __syncwarp();

    const float* vb = value + (long)b * STOT * DIM + warp*DH + lane;
    float acc = 0.f;
    for (int lp = 0; lp < 32; lp++) {
#pragma unroll
        for (int c = 0; c < 4; c++) {
            float wgt = s_w[warp][lp][c];
            if (wgt != 0.f)
                acc = fmaf(wgt, vb[(long)s_i[warp][lp][c] << 8], acc);
        }
    }
    ca_in[(long)bq*DIM + warp*DH + lane] = acc;
}

// ---------------- host orchestration ----------------
extern "C" void kernel_launch(void* const* d_in, const int* in_sizes, int n_in,
                              void* d_out, int out_size)
{
    const float* tgt        = (const float*)d_in[0];
    const float* qmask      = (const float*)d_in[1];
    const float* bbox       = (const float*)d_in[2];
    const float* memory     = (const float*)d_in[4];
    const float* in_proj_w  = (const float*)d_in[5];
    const float* in_proj_b  = (const float*)d_in[6];
    const float* out_sa_w   = (const float*)d_in[7];
    const float* out_sa_b   = (const float*)d_in[8];
    const float* norm2_g    = (const float*)d_in[9];
    const float* norm2_b    = (const float*)d_in[10];
    const float* value_w    = (const float*)d_in[11];
    const float* value_b    = (const float*)d_in[12];
    const float* off_w      = (const float*)d_in[13];
    const float* off_b      = (const float*)d_in[14];
    const float* aw_w       = (const float*)d_in[15];
    const float* aw_b       = (const float*)d_in[16];
    const float* out_ca_w   = (const float*)d_in[17];
    const float* out_ca_b   = (const float*)d_in[18];
    const float* norm1_g    = (const float*)d_in[19];
    const float* norm1_b    = (const float*)d_in[20];
    const float* lin1_w     = (const float*)d_in[21];
    const float* lin1_b     = (const float*)d_in[22];
    const float* lin2_w     = (const float*)d_in[23];
    const float* lin2_b     = (const float*)d_in[24];
    const float* norm3_g    = (const float*)d_in[25];
    const float* norm3_b    = (const float*)d_in[26];
    const unsigned char* pmask = (const unsigned char*)d_in[27];
    const int* spatial      = (const int*)d_in[28];
    const int* lstart       = (const int*)d_in[29];
    float* out = (float*)d_out;

    float *qbuf,*qh,*kh,*vh,*sain,*saout,*tgt2,*q2,*offb,*val,*cain,*caout,*tgt3,*f1,*f2;
    cudaGetSymbolAddress((void**)&qbuf,  g_qbuf);
    cudaGetSymbolAddress((void**)&qh,    g_qh);
    cudaGetSymbolAddress((void**)&kh,    g_kh);
    cudaGetSymbolAddress((void**)&vh,    g_vh);
    cudaGetSymbolAddress((void**)&sain,  g_sain);
    cudaGetSymbolAddress((void**)&saout, g_saout);
    cudaGetSymbolAddress((void**)&tgt2,  g_tgt2);
    cudaGetSymbolAddress((void**)&q2,    g_q2);
    cudaGetSymbolAddress((void**)&offb,  g_off);
    cudaGetSymbolAddress((void**)&val,   g_value);
    cudaGetSymbolAddress((void**)&cain,  g_cain);
    cudaGetSymbolAddress((void**)&caout, g_caout);
    cudaGetSymbolAddress((void**)&tgt3,  g_tgt3);
    cudaGetSymbolAddress((void**)&f1,    g_f1);
    cudaGetSymbolAddress((void**)&f2,    g_f2);

    // 1) q = tgt + query_mask
    add_kernel<<<TOKF/4/256, 256>>>(tgt, qmask, qbuf, TOKF/4);

    // 2) value projection over memory (batched over BS), pad-mask epilogue
    launch_mma(3, memory, BSZ*DIM, 256, value_w, DIM, value_b,
               nullptr, nullptr, 0,
               val, nullptr, DIM, (long)STOT*DIM,
               STOT, DIM, DIM, BSZ, pmask, STOT);

    // 3) Q+K merged (N=512; in_proj_w rows 0..511 contiguous), then V
    launch_mma(2, qbuf, DIM, 0, in_proj_w, DIM, in_proj_b,
               nullptr, nullptr, 0, qh, kh, 0, 0, NTOK, 512, DIM, 1, nullptr, 0);
    launch_mma(2, tgt, DIM, 0, in_proj_w + 512*256, DIM, in_proj_b + 512,
               nullptr, nullptr, 0, vh, nullptr, 0, 0, NTOK, DIM, DIM, 1, nullptr, 0);

    // 4) fused self-attention
    {
        int smem = (300*36*2 + 150*32 + 8*320) * 4;
        cudaFuncSetAttribute(attn_kernel, cudaFuncAttributeMaxDynamicSharedMemorySize, smem);
        attn_kernel<<<128, 256, smem>>>(qh, kh, vh, sain);
    }

    // 5) self-attn out-proj + residual LN (norm2)
    launch_mma(0, sain, DIM, 0, out_sa_w, DIM, out_sa_b,
               nullptr, nullptr, 0, saout, nullptr, DIM, 0, NTOK, DIM, DIM, 1, nullptr, 0);
    ln_kernel<<<NTOK/8, 256>>>(tgt, saout, 0, norm2_g, norm2_b, tgt2);

    // 6) query2 = (tgt2 + mask) in (b,q,d) layout
    permadd_kernel<<<(TOKF/4 + 255)/256, 256>>>(tgt2, qmask, q2);

    // 7) offsets + aw logits merged (N=768, W split at 512)
    launch_mma(0, q2, DIM, 0, off_w, DIM, off_b,
               aw_w, aw_b, 512,
               offb, nullptr, 768, 0, NTOK, 768, DIM, 1, nullptr, 0);

    // 8) deformable sampling
    deform_kernel<<<NTOK, 256>>>(offb, bbox, val, spatial, lstart, cain);

    // 9) cross-attn out-proj + residual LN (norm1)
    launch_mma(0, cain, DIM, 0, out_ca_w, DIM, out_ca_b,
               nullptr, nullptr, 0, caout, nullptr, DIM, 0, NTOK, DIM, DIM, 1, nullptr, 0);
    ln_kernel<<<NTOK/8, 256>>>(tgt2, caout, 1, norm1_g, norm1_b, tgt3);

    // 10) FFN + final LN (norm3) -> d_out
    launch_mma(1, tgt3, DIM, 0, lin1_w, DIM, lin1_b,
               nullptr, nullptr, 0, f1, nullptr, DFF, 0, NTOK, DFF, DIM, 1, nullptr, 0);
    launch_mma(0, f1, DFF, 0, lin2_w, DFF, lin2_b,
               nullptr, nullptr, 0, f2, nullptr, DIM, 0, NTOK, DIM, DFF, 1, nullptr, 0);
    ln_kernel<<<NTOK/8, 256>>>(tgt3, f2, 0, norm3_g, norm3_b, out);
}